// round 1
// baseline (speedup 1.0000x reference)
#include <cuda_runtime.h>

// SNN LIF-neuron spike count.
//   syn = 0.9*syn + x[t]; mem = 0.95*mem + syn;
//   s = (mem > 1); count += s; mem *= (1-s);
// Elementwise over B*N, sequential over T. Pure HBM-streaming kernel:
// 256 MiB read-once of x, tiny state. float4 vectorized, unrolled for MLP.

#define ALPHA 0.9f
#define BETA  0.95f

__global__ void __launch_bounds__(256)
snn_count_kernel(const float4* __restrict__ x,
                 const float4* __restrict__ mem0,
                 const float4* __restrict__ syn0,
                 const float4* __restrict__ count0,
                 float4* __restrict__ out,
                 int stride4,   // (B*N)/4 : float4 stride between timesteps
                 int T)
{
    int i = blockIdx.x * blockDim.x + threadIdx.x;
    if (i >= stride4) return;

    float4 syn = syn0[i];
    float4 mem = mem0[i];
    float4 cnt = count0[i];

    const float4* xp = x + i;

    #pragma unroll 8
    for (int t = 0; t < T; t++) {
        float4 xv = __ldg(xp);
        xp += stride4;

        // component x
        syn.x = fmaf(ALPHA, syn.x, xv.x);
        mem.x = fmaf(BETA,  mem.x, syn.x);
        {
            float s = (mem.x > 1.0f) ? 1.0f : 0.0f;
            cnt.x += s;
            mem.x *= (1.0f - s);
        }
        // component y
        syn.y = fmaf(ALPHA, syn.y, xv.y);
        mem.y = fmaf(BETA,  mem.y, syn.y);
        {
            float s = (mem.y > 1.0f) ? 1.0f : 0.0f;
            cnt.y += s;
            mem.y *= (1.0f - s);
        }
        // component z
        syn.z = fmaf(ALPHA, syn.z, xv.z);
        mem.z = fmaf(BETA,  mem.z, syn.z);
        {
            float s = (mem.z > 1.0f) ? 1.0f : 0.0f;
            cnt.z += s;
            mem.z *= (1.0f - s);
        }
        // component w
        syn.w = fmaf(ALPHA, syn.w, xv.w);
        mem.w = fmaf(BETA,  mem.w, syn.w);
        {
            float s = (mem.w > 1.0f) ? 1.0f : 0.0f;
            cnt.w += s;
            mem.w *= (1.0f - s);
        }
    }

    out[i] = cnt;
}

extern "C" void kernel_launch(void* const* d_in, const int* in_sizes, int n_in,
                              void* d_out, int out_size)
{
    const float* x      = (const float*)d_in[0];   // (T, B, N)
    const float* mem0   = (const float*)d_in[1];   // (B, N)
    const float* syn0   = (const float*)d_in[2];   // (B, N)
    const float* count0 = (const float*)d_in[3];   // (B, N)
    float* out          = (float*)d_out;           // (B, N)

    int BN = in_sizes[1];           // B*N
    int T  = in_sizes[0] / BN;      // timesteps

    int stride4 = BN / 4;
    int threads = 256;
    int blocks  = (stride4 + threads - 1) / threads;

    snn_count_kernel<<<blocks, threads>>>(
        (const float4*)x, (const float4*)mem0, (const float4*)syn0,
        (const float4*)count0, (float4*)out, stride4, T);
}

// round 2
// speedup vs baseline: 1.0419x; 1.0419x over previous
#include <cuda_runtime.h>

// SNN LIF-neuron spike count — HBM-streaming kernel (256 MiB read-once).
// R2 changes vs R1:
//   * 128-thread blocks -> 1024 blocks: fixes the 3.46/4 wave imbalance
//     (86% ceiling) seen at grid=512; now 6.92/7 = 99%.
//   * unroll 16 (was 8): doubles outstanding LDG.128 per warp to better
//     hide DRAM latency (issue% was 26.6, warps parked on long scoreboard).

#define ALPHA 0.9f
#define BETA  0.95f

__device__ __forceinline__ void lif_step(float xv, float& syn, float& mem, float& cnt)
{
    syn = fmaf(ALPHA, syn, xv);
    mem = fmaf(BETA,  mem, syn);
    float s = (mem > 1.0f) ? 1.0f : 0.0f;
    cnt += s;
    mem *= (1.0f - s);
}

__global__ void __launch_bounds__(128)
snn_count_kernel(const float4* __restrict__ x,
                 const float4* __restrict__ mem0,
                 const float4* __restrict__ syn0,
                 const float4* __restrict__ count0,
                 float4* __restrict__ out,
                 int stride4,   // (B*N)/4 : float4 stride between timesteps
                 int T)
{
    int i = blockIdx.x * blockDim.x + threadIdx.x;
    if (i >= stride4) return;

    float4 syn = syn0[i];
    float4 mem = mem0[i];
    float4 cnt = count0[i];

    const float4* xp = x + i;

    #pragma unroll 16
    for (int t = 0; t < T; t++) {
        float4 xv = __ldg(xp);
        xp += stride4;

        lif_step(xv.x, syn.x, mem.x, cnt.x);
        lif_step(xv.y, syn.y, mem.y, cnt.y);
        lif_step(xv.z, syn.z, mem.z, cnt.z);
        lif_step(xv.w, syn.w, mem.w, cnt.w);
    }

    out[i] = cnt;
}

extern "C" void kernel_launch(void* const* d_in, const int* in_sizes, int n_in,
                              void* d_out, int out_size)
{
    const float* x      = (const float*)d_in[0];   // (T, B, N)
    const float* mem0   = (const float*)d_in[1];   // (B, N)
    const float* syn0   = (const float*)d_in[2];   // (B, N)
    const float* count0 = (const float*)d_in[3];   // (B, N)
    float* out          = (float*)d_out;           // (B, N)

    int BN = in_sizes[1];           // B*N
    int T  = in_sizes[0] / BN;      // timesteps

    int stride4 = BN / 4;
    int threads = 128;
    int blocks  = (stride4 + threads - 1) / threads;

    snn_count_kernel<<<blocks, threads>>>(
        (const float4*)x, (const float4*)mem0, (const float4*)syn0,
        (const float4*)count0, (float4*)out, stride4, T);
}

// round 3
// speedup vs baseline: 1.1332x; 1.0877x over previous
#include <cuda_runtime.h>

// SNN LIF-neuron spike count — HBM-streaming kernel (256 MiB read-once).
// R3 changes vs R2:
//   * Explicit 8-deep float4 prefetch buffer: ptxas previously collapsed the
//     unroll (regs=38 => MLP~2). buf[8] forces 8 back-to-back LDG.128 per
//     warp before any consumer -> real memory-level parallelism.
//   * __ldcs (streaming / evict-first): data is read exactly once.

#define ALPHA 0.9f
#define BETA  0.95f

__device__ __forceinline__ void lif_step(float xv, float& syn, float& mem, float& cnt)
{
    syn = fmaf(ALPHA, syn, xv);
    mem = fmaf(BETA,  mem, syn);
    float s = (mem > 1.0f) ? 1.0f : 0.0f;
    cnt += s;
    mem *= (1.0f - s);
}

__global__ void __launch_bounds__(128)
snn_count_kernel(const float4* __restrict__ x,
                 const float4* __restrict__ mem0,
                 const float4* __restrict__ syn0,
                 const float4* __restrict__ count0,
                 float4* __restrict__ out,
                 int stride4,   // (B*N)/4 : float4 stride between timesteps
                 int T)
{
    int i = blockIdx.x * blockDim.x + threadIdx.x;
    if (i >= stride4) return;

    float4 syn = syn0[i];
    float4 mem = mem0[i];
    float4 cnt = count0[i];

    const float4* xp = x + i;

    const int UB = 8;               // prefetch depth (T=128 divisible by 8)
    float4 buf[UB];

    for (int tb = 0; tb < T; tb += UB) {
        // Batch-issue 8 independent LDG.128 (no consumer in between).
        #pragma unroll
        for (int u = 0; u < UB; u++)
            buf[u] = __ldcs(xp + u * stride4);
        xp += UB * stride4;

        // Consume the batch through the serial recurrence.
        #pragma unroll
        for (int u = 0; u < UB; u++) {
            lif_step(buf[u].x, syn.x, mem.x, cnt.x);
            lif_step(buf[u].y, syn.y, mem.y, cnt.y);
            lif_step(buf[u].z, syn.z, mem.z, cnt.z);
            lif_step(buf[u].w, syn.w, mem.w, cnt.w);
        }
    }

    out[i] = cnt;
}

extern "C" void kernel_launch(void* const* d_in, const int* in_sizes, int n_in,
                              void* d_out, int out_size)
{
    const float* x      = (const float*)d_in[0];   // (T, B, N)
    const float* mem0   = (const float*)d_in[1];   // (B, N)
    const float* syn0   = (const float*)d_in[2];   // (B, N)
    const float* count0 = (const float*)d_in[3];   // (B, N)
    float* out          = (float*)d_out;           // (B, N)

    int BN = in_sizes[1];           // B*N
    int T  = in_sizes[0] / BN;      // timesteps

    int stride4 = BN / 4;
    int threads = 128;
    int blocks  = (stride4 + threads - 1) / threads;

    snn_count_kernel<<<blocks, threads>>>(
        (const float4*)x, (const float4*)mem0, (const float4*)syn0,
        (const float4*)count0, (float4*)out, stride4, T);
}

// round 4
// speedup vs baseline: 1.1882x; 1.0485x over previous
#include <cuda_runtime.h>

// SNN LIF spike-count — HBM-streaming (256 MiB read-once).
// R4: ptxas kept collapsing the prefetch buffer (regs=38 => MLP~2).
// Fix: asm-volatile v4 loads (un-sinkable, ordered) + depth-4 double
// buffering so every load issues a full batch ahead of its consumer.

#define ALPHA 0.9f
#define BETA  0.95f

#define LOADCS4(dst, ptr)                                             \
    asm volatile("ld.global.cs.v4.f32 {%0,%1,%2,%3}, [%4];"           \
                 : "=f"((dst).x), "=f"((dst).y),                      \
                   "=f"((dst).z), "=f"((dst).w)                       \
                 : "l"(ptr))

__device__ __forceinline__ void lif_step(float xv, float& syn, float& mem, float& cnt)
{
    syn = fmaf(ALPHA, syn, xv);
    mem = fmaf(BETA,  mem, syn);
    float s = (mem > 1.0f) ? 1.0f : 0.0f;
    cnt += s;
    mem *= (1.0f - s);
}

__device__ __forceinline__ void consume4(const float4* buf,
                                         float4& syn, float4& mem, float4& cnt)
{
    #pragma unroll
    for (int u = 0; u < 4; u++) {
        lif_step(buf[u].x, syn.x, mem.x, cnt.x);
        lif_step(buf[u].y, syn.y, mem.y, cnt.y);
        lif_step(buf[u].z, syn.z, mem.z, cnt.z);
        lif_step(buf[u].w, syn.w, mem.w, cnt.w);
    }
}

__global__ void __launch_bounds__(128)
snn_count_kernel(const float4* __restrict__ x,
                 const float4* __restrict__ mem0,
                 const float4* __restrict__ syn0,
                 const float4* __restrict__ count0,
                 float4* __restrict__ out,
                 int stride4,   // (B*N)/4 : float4 stride between timesteps
                 int T)         // multiple of 8
{
    int i = blockIdx.x * blockDim.x + threadIdx.x;
    if (i >= stride4) return;

    float4 syn = syn0[i];
    float4 mem = mem0[i];
    float4 cnt = count0[i];

    const float4* xp = x + i;
    long ls = stride4;             // 64-bit stride for address math

    float4 bufA[4], bufB[4];

    // Prologue: batch 0 -> A
    #pragma unroll
    for (int u = 0; u < 4; u++) LOADCS4(bufA[u], xp + u * ls);
    xp += 4 * ls;

    // Steady state: always load the next batch before consuming the current.
    int t = 4;
    for (; t + 8 <= T; t += 8) {
        #pragma unroll
        for (int u = 0; u < 4; u++) LOADCS4(bufB[u], xp + u * ls);
        xp += 4 * ls;
        consume4(bufA, syn, mem, cnt);

        #pragma unroll
        for (int u = 0; u < 4; u++) LOADCS4(bufA[u], xp + u * ls);
        xp += 4 * ls;
        consume4(bufB, syn, mem, cnt);
    }

    // Epilogue: one batch left (t == T-4), A holds t-4..t-1.
    #pragma unroll
    for (int u = 0; u < 4; u++) LOADCS4(bufB[u], xp + u * ls);
    consume4(bufA, syn, mem, cnt);
    consume4(bufB, syn, mem, cnt);

    out[i] = cnt;
}

extern "C" void kernel_launch(void* const* d_in, const int* in_sizes, int n_in,
                              void* d_out, int out_size)
{
    const float* x      = (const float*)d_in[0];   // (T, B, N)
    const float* mem0   = (const float*)d_in[1];   // (B, N)
    const float* syn0   = (const float*)d_in[2];   // (B, N)
    const float* count0 = (const float*)d_in[3];   // (B, N)
    float* out          = (float*)d_out;           // (B, N)

    int BN = in_sizes[1];           // B*N
    int T  = in_sizes[0] / BN;      // timesteps

    int stride4 = BN / 4;
    int threads = 128;
    int blocks  = (stride4 + threads - 1) / threads;

    snn_count_kernel<<<blocks, threads>>>(
        (const float4*)x, (const float4*)mem0, (const float4*)syn0,
        (const float4*)count0, (float4*)out, stride4, T);
}